// round 4
// baseline (speedup 1.0000x reference)
#include <cuda_runtime.h>
#include <math.h>

// Shapes fixed by the problem instance (verified against setup_inputs):
// b=4 graphs, n=128 nodes, f=32 features, layer channels 64.
#define BG   4
#define NN   128
#define FF   32
#define ECH  64
#define NPAD 129
#define NSQ  (NN*NN)

// ---------------- device scratch (no allocations allowed) ----------------
__device__ float g_A [BG*NSQ];
__device__ float g_G [BG*NSQ];   // A A^T
__device__ float g_H [BG*NSQ];   // A^T A
__device__ float g_M2[BG*NSQ];   // A A
__device__ float g_ra[BG*NN];    // row sums of A
__device__ float g_ca[BG*NN];    // col sums of A
__device__ float g_U [BG*FF*NN]; // x2 = x reshaped [b,f,n]
__device__ float g_UA[BG*FF*NN]; // U·A   (UA[d,j] = sum_i U[d,i]A[i,j])
__device__ float g_Au[BG*FF*NN]; // A·u   (Au[d,i] = sum_j A[i,j]U[d,j])
__device__ float g_su[BG*FF];    // sum_i U[d,i]

// per-(b,e) vectors over positions (length NN each)
__device__ float g_p01 [BG*ECH*NN];
__device__ float g_p2c [BG*ECH*NN];
__device__ float g_p3c [BG*ECH*NN];
__device__ float g_gI  [BG*ECH*NN];
__device__ float g_gJ  [BG*ECH*NN];
__device__ float g_hI  [BG*ECH*NN];
__device__ float g_hJ  [BG*ECH*NN];
__device__ float g_mI  [BG*ECH*NN];
__device__ float g_mJ  [BG*ECH*NN];
__device__ float g_t14 [BG*ECH*NN];
__device__ float g_t13 [BG*ECH*NN];
__device__ float g_t911[BG*ECH*NN];
__device__ float g_t1012[BG*ECH*NN];
__device__ float g_Ri  [BG*ECH*NN];
__device__ float g_Rj  [BG*ECH*NN];
__device__ float g_s   [BG*ECH];

// layer-2 collapsed weights: [7][ECH]
__device__ float g_w[7*ECH];
__device__ float g_b2sum;
__device__ float g_part[BG*NN];

__device__ __forceinline__ float warpSum(float v) {
    #pragma unroll
    for (int o = 16; o; o >>= 1) v += __shfl_down_sync(0xffffffffu, v, o);
    return v;
}

// ---------------- kernels ----------------
__global__ void k_zeroA() {
    int idx = blockIdx.x * blockDim.x + threadIdx.x;
    if (idx < BG*NSQ) g_A[idx] = 0.0f;
}

__global__ void k_scatter(const int* __restrict__ ei, const float* __restrict__ ew,
                          const int* __restrict__ batch, int ne) {
    int idx = blockIdx.x * blockDim.x + threadIdx.x;
    if (idx >= ne) return;
    int s = ei[idx];
    int t = ei[ne + idx];
    int g = batch[s];
    int r = s - g*NN;
    int c = t - g*NN;
    atomicAdd(&g_A[(g*NN + r)*NN + c], ew[idx]);
}

// per (b,i): G/H/M2 row i, ra[i]; block i==0: ca; block i==1: U
__global__ void k_prep1(const float* __restrict__ x) {
    extern __shared__ float sA[];
    int b = blockIdx.y, i = blockIdx.x, tid = threadIdx.x;
    const float* Ab = g_A + b*NSQ;
    for (int idx = tid; idx < NSQ; idx += 128)
        sA[(idx >> 7)*NPAD + (idx & 127)] = Ab[idx];
    __syncthreads();
    int j = tid;
    float gv = 0.f, hv = 0.f, mv = 0.f;
    #pragma unroll 4
    for (int k = 0; k < NN; k++) {
        float aik = sA[i*NPAD + k];
        gv = fmaf(aik,            sA[j*NPAD + k], gv);
        hv = fmaf(sA[k*NPAD + i], sA[k*NPAD + j], hv);
        mv = fmaf(aik,            sA[k*NPAD + j], mv);
    }
    int o = b*NSQ + i*NN + j;
    g_G[o] = gv; g_H[o] = hv; g_M2[o] = mv;

    __shared__ float red[4];
    float v = warpSum(sA[i*NPAD + tid]);
    if ((tid & 31) == 0) red[tid >> 5] = v;
    __syncthreads();
    if (tid == 0) g_ra[b*NN + i] = red[0] + red[1] + red[2] + red[3];

    if (i == 0) {
        float s = 0.f;
        for (int m = 0; m < NN; m++) s += sA[m*NPAD + j];
        g_ca[b*NN + j] = s;
    }
    if (i == 1) {
        for (int idx = tid; idx < FF*NN; idx += 128) {
            int d = idx >> 7, p = idx & 127;
            g_U[b*FF*NN + idx] = x[(b*NN + p)*FF + d];
        }
    }
}

// per (b,d): UA, Au, su
__global__ void k_prep2() {
    int b = blockIdx.y, d = blockIdx.x, pos = threadIdx.x;
    const float* Ab = g_A + b*NSQ;
    const float* Ud = g_U + (b*FF + d)*NN;
    float ua = 0.f, au = 0.f;
    #pragma unroll 4
    for (int m = 0; m < NN; m++) {
        float um = Ud[m];
        ua = fmaf(um, Ab[m*NN + pos], ua);
        au = fmaf(Ab[pos*NN + m], um, au);
    }
    g_UA[(b*FF + d)*NN + pos] = ua;
    g_Au[(b*FF + d)*NN + pos] = au;
    __shared__ float red[4];
    float v = warpSum(Ud[pos]);
    if ((pos & 31) == 0) red[pos >> 5] = v;
    __syncthreads();
    if (pos == 0) g_su[b*FF + d] = red[0] + red[1] + red[2] + red[3];
}

// per (b,e): contract coeffs1 with U/UA/Au into position vectors
__global__ void k_prep3(const float* __restrict__ c1) {
    int b = blockIdx.y, e = blockIdx.x, i = threadIdx.x;
    __shared__ float sc[64*20];
    for (int idx = threadIdx.x; idx < 64*20; idx += 128) {
        int d = idx / 20, r = idx % 20;
        sc[idx] = c1[d*(ECH*20) + e*20 + r];
    }
    __syncthreads();

    float p01=0, p2c=0, p3c=0, gI=0, gJ=0, hI=0, hJ=0, mI=0, mJ=0;
    float t14=0, t13=0, t911=0, t1012=0;
    float ri_ra=0, ri_uA=0, ri_n=0, ri_Au=0, ri_ca=0, ri_n2=0;
    float rj_ra=0, rj_uA=0, rj_n=0, rj_Au=0, rj_ca=0, rj_ra2=0, rj_n2=0;

    for (int d = 0; d < FF; d++) {
        float u  = g_U [(b*FF + d)*NN + i];
        float ua = g_UA[(b*FF + d)*NN + i];
        float au = g_Au[(b*FF + d)*NN + i];
        const float* cr = sc + d*20;          // row-half coeffs (d < 32)
        const float* cc = sc + (d + 32)*20;   // col-half coeffs
        // row-half
        p01   = fmaf(cr[0] + cr[1], u, p01);
        mI    = fmaf(cr[2], u, mI);
        mJ    = fmaf(cr[3], u, mJ);
        gI    = fmaf(cr[4], u, gI);
        ri_ra = fmaf(cr[5] + cr[13], u, ri_ra);
        rj_ra = fmaf(cr[6], u, rj_ra);
        rj_uA = fmaf(cr[7] + cr[9] + cr[11], ua, rj_uA);
        ri_uA = fmaf(cr[8] + cr[10] + cr[12], ua, ri_uA);
        t14   = fmaf(cr[14], u, t14);
        ri_n  = fmaf(cr[15] + cr[19], u, ri_n);   // x N
        rj_n  = fmaf(cr[16], u, rj_n);            // x N
        // col-half
        hI    = fmaf(cc[0], u, hI);
        hJ    = fmaf(cc[1], u, hJ);
        p2c   = fmaf(cc[2], u, p2c);
        p3c   = fmaf(cc[3], u, p3c);
        gJ    = fmaf(cc[4], u, gJ);
        ri_Au = fmaf(cc[5], au, ri_Au);
        rj_Au = fmaf(cc[6], au, rj_Au);
        rj_ca = fmaf(cc[7], u, rj_ca);
        ri_ca = fmaf(cc[8], u, ri_ca);
        t911  = fmaf(cc[9] + cc[11], u, t911);
        t1012 = fmaf(cc[10] + cc[12], u, t1012);
        t13   = fmaf(cc[13], u, t13);
        rj_ra2= fmaf(cc[14], u, rj_ra2);
        rj_n2 = fmaf(cc[17] + cc[19], u, rj_n2);  // x N
        ri_n2 = fmaf(cc[18], u, ri_n2);           // x N
    }
    float rai = g_ra[b*NN + i], cai = g_ca[b*NN + i];
    float Ri = rai*ri_ra + ri_uA + (float)NN*(ri_n + ri_n2) + ri_Au + cai*ri_ca;
    float Rj = rai*(rj_ra + rj_ra2) + rj_uA + (float)NN*(rj_n + rj_n2) + rj_Au + cai*rj_ca;

    int base = (b*ECH + e)*NN + i;
    g_p01[base]=p01; g_p2c[base]=p2c; g_p3c[base]=p3c;
    g_gI[base]=gI; g_gJ[base]=gJ; g_hI[base]=hI; g_hJ[base]=hJ;
    g_mI[base]=mI; g_mJ[base]=mJ;
    g_t14[base]=t14; g_t13[base]=t13; g_t911[base]=t911; g_t1012[base]=t1012;
    g_Ri[base]=Ri; g_Rj[base]=Rj;

    if (i == 0) {
        float s = 0.f;
        for (int d = 0; d < FF; d++) {
            float w = sc[d*20 + 17] + sc[d*20 + 18]
                    + sc[(d+32)*20 + 15] + sc[(d+32)*20 + 16];
            s = fmaf(w, g_su[b*FF + d], s);
        }
        g_s[b*ECH + e] = s;
    }
}

// layer-2 collapsed weights
__global__ void k_prep4(const float* __restrict__ c2, const float* __restrict__ b2) {
    int d = threadIdx.x;
    if (d < ECH) {
        float cs[20];
        #pragma unroll
        for (int r = 0; r < 20; r++) cs[r] = 0.f;
        for (int e = 0; e < ECH; e++) {
            const float* p = c2 + d*(ECH*20) + e*20;
            #pragma unroll
            for (int r = 0; r < 20; r++) cs[r] += p[r];
        }
        float invn = 1.0f / (float)NN;
        g_w[0*ECH + d] = cs[15]+cs[16]+cs[17]+cs[18]+cs[19];        // w_T
        g_w[1*ECH + d] = cs[5]+cs[6]+cs[7]+cs[8];                   // w_TA
        g_w[2*ECH + d] = cs[4]*invn;                                // w_TG
        g_w[3*ECH + d] = (cs[9]+cs[10]+cs[11]+cs[12]+cs[13])*invn;  // w_TzRi
        g_w[4*ECH + d] = cs[14]*invn;                               // w_TzRj
        g_w[5*ECH + d] = (cs[0]+cs[1])*invn;                        // w_TARi
        g_w[6*ECH + d] = (cs[2]+cs[3])*invn;                        // w_TARj
    }
    if (d == 0) {
        float s = 0.f;
        for (int e = 0; e < ECH; e++) s += b2[e];
        g_b2sum = s;
    }
}

// main fused kernel: per (b,i) block. phi[e,j] = P1·A + P2·A^T (GEMM),
// + elementwise terms, sigmoid, layer-2 weighted accumulate.
__global__ void __launch_bounds__(256, 2) k_main(const float* __restrict__ bias1) {
    extern __shared__ float sm[];
    float* sA  = sm;                      // [NN][NPAD]
    float* sP1 = sm + NN*NPAD;            // [ECH][64]
    float* sP2 = sP1 + ECH*64;            // [ECH][64]

    int b = blockIdx.y, i = blockIdx.x, tid = threadIdx.x;
    int te = tid >> 5, tj = tid & 31;

    const float* Ab = g_A + b*NSQ;
    for (int idx = tid; idx < NSQ; idx += 256)
        sA[(idx >> 7)*NPAD + (idx & 127)] = Ab[idx];
    __syncthreads();

    const float* pb1 = g_p01 + b*ECH*NN;
    const float* pb2 = g_p2c + b*ECH*NN;
    const float* pb3 = g_p3c + b*ECH*NN;

    float acc[8][4];
    #pragma unroll
    for (int a = 0; a < 8; a++)
        #pragma unroll
        for (int q = 0; q < 4; q++) acc[a][q] = 0.f;

    for (int ch = 0; ch < 2; ch++) {
        int m0 = ch * 64;
        for (int idx = tid; idx < ECH*64; idx += 256) {
            int e = idx >> 6, mm = idx & 63, m = m0 + mm;
            float ami = sA[m*NPAD + i];   // A[m,i]
            float aim = sA[i*NPAD + m];   // A[i,m]
            sP1[idx] = fmaf(pb1[e*NN + m], ami, pb2[e*NN + m]*aim);
            sP2[idx] = pb3[e*NN + m]*ami;
        }
        __syncthreads();
        #pragma unroll 2
        for (int mm = 0; mm < 64; mm++) {
            int m = m0 + mm;
            float cv[4], rv[4];
            #pragma unroll
            for (int q = 0; q < 4; q++) {
                cv[q] = sA[m*NPAD + tj + 32*q];       // A[m,j]
                rv[q] = sA[(tj + 32*q)*NPAD + m];     // A[j,m]
            }
            #pragma unroll
            for (int e8 = 0; e8 < 8; e8++) {
                float p1 = sP1[(te*8 + e8)*64 + mm];
                float p2 = sP2[(te*8 + e8)*64 + mm];
                #pragma unroll
                for (int q = 0; q < 4; q++)
                    acc[e8][q] = fmaf(p1, cv[q], fmaf(p2, rv[q], acc[e8][q]));
            }
        }
        __syncthreads();
    }

    // epilogue
    float rai = g_ra[b*NN + i], cai = g_ca[b*NN + i];
    float raj[4], caj[4], Gv[4], Hv[4], M2v[4], M2t[4], aij[4];
    #pragma unroll
    for (int q = 0; q < 4; q++) {
        int j = tj + 32*q;
        raj[q] = g_ra[b*NN + j];
        caj[q] = g_ca[b*NN + j];
        Gv[q]  = g_G [b*NSQ + i*NN + j];
        Hv[q]  = g_H [b*NSQ + i*NN + j];
        M2v[q] = g_M2[b*NSQ + i*NN + j];
        M2t[q] = g_M2[b*NSQ + j*NN + i];
        aij[q] = sA[i*NPAD + j];
    }

    const float invn = 1.0f / (float)NN;
    float accout = 0.f;
    #pragma unroll
    for (int e8 = 0; e8 < 8; e8++) {
        int e = te*8 + e8;
        int base = (b*ECH + e)*NN;
        float gIi  = g_gI [base + i];
        float hIi  = g_hI [base + i];
        float mIi  = g_mI [base + i];
        float t14i = g_t14[base + i];
        float t9i  = g_t911[base + i];
        float Rii  = g_Ri [base + i];
        float sv   = g_s[b*ECH + e];
        float b1   = bias1[e];
        float wT    = g_w[0*ECH + e];
        float wTA   = g_w[1*ECH + e];
        float wTG   = g_w[2*ECH + e];
        float wTzRi = g_w[3*ECH + e];
        float wTzRj = g_w[4*ECH + e];
        float wTARi = g_w[5*ECH + e];
        float wTARj = g_w[6*ECH + e];
        #pragma unroll
        for (int q = 0; q < 4; q++) {
            int j = tj + 32*q;
            float phi = acc[e8][q]
                + Gv[q]  * (gIi + g_gJ[base + j])
                + Hv[q]  * (hIi + g_hJ[base + j])
                + M2v[q] * mIi + M2t[q] * g_mJ[base + j]
                + Rii + g_Rj[base + j]
                + raj[q] * t14i + rai * g_t13[base + j]
                + caj[q] * t9i  + cai * g_t1012[base + j]
                + sv;
            float pre = fmaf(phi, invn, b1);
            float z = __fdividef(1.0f, 1.0f + __expf(-pre));
            float w = wT + wTA*aij[q] + wTG*Gv[q]
                    + rai    * fmaf(wTARi, aij[q], wTzRi)
                    + raj[q] * fmaf(wTARj, aij[q], wTzRj);
            accout = fmaf(z, w, accout);
        }
    }

    __shared__ float red[8];
    float v = warpSum(accout);
    if ((tid & 31) == 0) red[tid >> 5] = v;
    __syncthreads();
    if (tid == 0) {
        float s = 0.f;
        #pragma unroll
        for (int w8 = 0; w8 < 8; w8++) s += red[w8];
        g_part[b*NN + i] = s;
    }
}

__global__ void k_final(float* __restrict__ out) {
    int tid = threadIdx.x;
    __shared__ float red[4];
    for (int b = 0; b < BG; b++) {
        float v = warpSum(g_part[b*NN + tid]);
        if ((tid & 31) == 0) red[tid >> 5] = v;
        __syncthreads();
        if (tid == 0) {
            float total = red[0] + red[1] + red[2] + red[3];
            out[b] = (total + (float)NSQ * g_b2sum) * (1.0f / (float)(ECH*NSQ));
        }
        __syncthreads();
    }
}

// ---------------- launch ----------------
extern "C" void kernel_launch(void* const* d_in, const int* in_sizes, int n_in,
                              void* d_out, int out_size) {
    const float* x   = (const float*)d_in[0];
    const float* ew  = (const float*)d_in[1];
    const float* c1  = (const float*)d_in[2];
    const float* b1  = (const float*)d_in[3];
    const float* c2  = (const float*)d_in[4];
    const float* b2  = (const float*)d_in[5];
    const int*   ei  = (const int*)  d_in[6];
    const int*   bat = (const int*)  d_in[7];
    float* out = (float*)d_out;
    int ne = in_sizes[1];

    static bool attr_done = false;
    if (!attr_done) {
        cudaFuncSetAttribute(k_prep1, cudaFuncAttributeMaxDynamicSharedMemorySize,
                             NN*NPAD*(int)sizeof(float));
        cudaFuncSetAttribute(k_main, cudaFuncAttributeMaxDynamicSharedMemorySize,
                             (NN*NPAD + 2*ECH*64)*(int)sizeof(float));
        attr_done = true;
    }

    k_zeroA<<<(BG*NSQ + 255)/256, 256>>>();
    k_scatter<<<(ne + 255)/256, 256>>>(ei, ew, bat, ne);
    k_prep1<<<dim3(NN, BG), 128, NN*NPAD*sizeof(float)>>>(x);
    k_prep2<<<dim3(FF, BG), 128>>>();
    k_prep3<<<dim3(ECH, BG), 128>>>(c1);
    k_prep4<<<1, 64>>>(c2, b2);
    k_main<<<dim3(NN, BG), 256, (NN*NPAD + 2*ECH*64)*sizeof(float)>>>(b1);
    k_final<<<1, 128>>>(out);
    (void)n_in; (void)out_size;
}

// round 5
// speedup vs baseline: 1.7412x; 1.7412x over previous
#include <cuda_runtime.h>
#include <math.h>

// Shapes fixed by the problem instance:
// b=4 graphs, n=128 nodes, f=32 features, layer channels 64.
#define BG   4
#define NN   128
#define FF   32
#define ECH  64
#define NP   129
#define NSQ  (NN*NN)

typedef unsigned long long u64;

// ---------------- device scratch ----------------
__device__ float  g_A [BG*NSQ];
__device__ float4 g_GH[BG*NSQ];        // (G, H, M2, M2^T) at [b][i][j]
__device__ float  g_ra[BG*NN];
__device__ float  g_ca[BG*NN];
__device__ float  g_U [BG*FF*NN];
__device__ float  g_UA[BG*FF*NN];
__device__ float  g_Au[BG*FF*NN];
__device__ float  g_su[BG*FF];

// packed per-(b,e,pos) vectors
__device__ float4 g_P4[BG*ECH*NN];     // (p01, p2c, p3c, 0)
__device__ float4 g_I4[BG*ECH*NN];     // (gI, hI, mI, t14)
__device__ float2 g_I2[BG*ECH*NN];     // (t911, Ri)
__device__ float4 g_J4[BG*ECH*NN];     // (gJ, hJ, mJ, Rj)
__device__ float2 g_J2[BG*ECH*NN];     // (t13, t1012)
__device__ float  g_s [BG*ECH];

__device__ float g_w[7*ECH];
__device__ float g_b2sum;
__device__ float g_part[BG*NN];

__device__ __forceinline__ float warpSum(float v) {
    #pragma unroll
    for (int o = 16; o; o >>= 1) v += __shfl_down_sync(0xffffffffu, v, o);
    return v;
}
__device__ __forceinline__ u64 pk2(float lo, float hi) {
    u64 r; asm("mov.b64 %0, {%1, %2};" : "=l"(r) : "f"(lo), "f"(hi)); return r;
}
__device__ __forceinline__ float2 upk2(u64 v) {
    float2 f; asm("mov.b64 {%0, %1}, %2;" : "=f"(f.x), "=f"(f.y) : "l"(v)); return f;
}
__device__ __forceinline__ u64 fma2(u64 a, u64 b, u64 c) {
    u64 d; asm("fma.rn.f32x2 %0, %1, %2, %3;" : "=l"(d) : "l"(a), "l"(b), "l"(c)); return d;
}

// ---------------- kernels ----------------
__global__ void k_zeroA() {
    int idx = blockIdx.x * blockDim.x + threadIdx.x;
    if (idx < BG*NSQ) g_A[idx] = 0.0f;
}

__global__ void k_scatter(const int* __restrict__ ei, const float* __restrict__ ew,
                          const int* __restrict__ batch, int ne) {
    int idx = blockIdx.x * blockDim.x + threadIdx.x;
    if (idx >= ne) return;
    int s = ei[idx];
    int t = ei[ne + idx];
    int g = batch[s];
    int r = s - g*NN;
    int c = t - g*NN;
    atomicAdd(&g_A[(g*NN + r)*NN + c], ew[idx]);
}

// Fused: per (b, 8-row tile): G/H/M2/M2T, UA, Au, ra, ca; tile 0: su + g_U.
__global__ void __launch_bounds__(256, 2) k_prepA(const float* __restrict__ x) {
    extern __shared__ float sm[];
    float* sA = sm;              // [128][NP]
    float* sU = sm + NN*NP;      // [32][NP]
    int b = blockIdx.y, t = blockIdx.x, tid = threadIdx.x;
    const float* Ab = g_A + b*NSQ;
    for (int idx = tid; idx < NSQ; idx += 256)
        sA[(idx >> 7)*NP + (idx & 127)] = Ab[idx];
    for (int idx = tid; idx < FF*NN; idx += 256) {
        int d = idx & 31, m = idx >> 5;
        sU[d*NP + m] = x[(b*NN + m)*FF + d];
    }
    __syncthreads();

    int r = tid >> 5, lane = tid & 31;
    int i = 8*t + r;

    // G/H/M2/M2T rows i, all j (4 j per thread)
    float gv[4] = {0,0,0,0}, hv[4] = {0,0,0,0}, mv[4] = {0,0,0,0}, mt[4] = {0,0,0,0};
    #pragma unroll 4
    for (int k = 0; k < NN; k++) {
        float aik = sA[i*NP + k];   // A[i,k] uniform
        float aki = sA[k*NP + i];   // A[k,i] uniform
        #pragma unroll
        for (int q = 0; q < 4; q++) {
            int j = lane + 32*q;
            float ajk = sA[j*NP + k];
            float akj = sA[k*NP + j];
            gv[q] = fmaf(aik, ajk, gv[q]);
            hv[q] = fmaf(aki, akj, hv[q]);
            mv[q] = fmaf(aik, akj, mv[q]);
            mt[q] = fmaf(ajk, aki, mt[q]);
        }
    }
    #pragma unroll
    for (int q = 0; q < 4; q++) {
        int j = lane + 32*q;
        g_GH[b*NSQ + i*NN + j] = make_float4(gv[q], hv[q], mv[q], mt[q]);
    }

    // ra[i] (row sums), ca for tile cols
    {
        float p = 0.f;
        #pragma unroll
        for (int q = 0; q < 4; q++) p += sA[i*NP + lane + 32*q];
        p = warpSum(p);
        if (lane == 0) g_ra[b*NN + i] = p;
        int j0 = 8*t + r;
        float c = 0.f;
        #pragma unroll
        for (int q = 0; q < 4; q++) c += sA[(lane + 32*q)*NP + j0];
        c = warpSum(c);
        if (lane == 0) g_ca[b*NN + j0] = c;
    }

    // UA[d,j], Au[d,i2] for the 8 positions of this tile
    {
        int d = tid >> 3, p8 = tid & 7;
        int pos = 8*t + p8;
        float ua = 0.f, au = 0.f;
        #pragma unroll 4
        for (int m = 0; m < NN; m++) {
            float um = sU[d*NP + m];
            ua = fmaf(um, sA[m*NP + pos], ua);
            au = fmaf(sA[pos*NP + m], um, au);
        }
        g_UA[(b*FF + d)*NN + pos] = ua;
        g_Au[(b*FF + d)*NN + pos] = au;
    }

    if (t == 0) {
        for (int idx = tid; idx < FF*NN; idx += 256)
            g_U[b*FF*NN + idx] = sU[(idx >> 7)*NP + (idx & 127)];
        if (tid < FF) {
            float s = 0.f;
            for (int m = 0; m < NN; m++) s += sU[tid*NP + m];
            g_su[b*FF + tid] = s;
        }
    }
}

// per (b,e): contract coeffs1 with U/UA/Au into packed position vectors
__global__ void k_prepV(const float* __restrict__ c1) {
    int b = blockIdx.y, e = blockIdx.x, i = threadIdx.x;
    __shared__ float sc[64*20];
    for (int idx = threadIdx.x; idx < 64*20; idx += 128) {
        int d = idx / 20, r = idx % 20;
        sc[idx] = c1[d*(ECH*20) + e*20 + r];
    }
    __syncthreads();

    float p01=0, p2c=0, p3c=0, gI=0, gJ=0, hI=0, hJ=0, mI=0, mJ=0;
    float t14=0, t13=0, t911=0, t1012=0;
    float ri_ra=0, ri_uA=0, ri_n=0, ri_Au=0, ri_ca=0, ri_n2=0;
    float rj_ra=0, rj_uA=0, rj_n=0, rj_Au=0, rj_ca=0, rj_ra2=0, rj_n2=0;

    #pragma unroll 4
    for (int d = 0; d < FF; d++) {
        float u  = g_U [(b*FF + d)*NN + i];
        float ua = g_UA[(b*FF + d)*NN + i];
        float au = g_Au[(b*FF + d)*NN + i];
        const float* cr = sc + d*20;
        const float* cc = sc + (d + 32)*20;
        p01   = fmaf(cr[0] + cr[1], u, p01);
        mI    = fmaf(cr[2], u, mI);
        mJ    = fmaf(cr[3], u, mJ);
        gI    = fmaf(cr[4], u, gI);
        ri_ra = fmaf(cr[5] + cr[13], u, ri_ra);
        rj_ra = fmaf(cr[6], u, rj_ra);
        rj_uA = fmaf(cr[7] + cr[9] + cr[11], ua, rj_uA);
        ri_uA = fmaf(cr[8] + cr[10] + cr[12], ua, ri_uA);
        t14   = fmaf(cr[14], u, t14);
        ri_n  = fmaf(cr[15] + cr[19], u, ri_n);
        rj_n  = fmaf(cr[16], u, rj_n);
        hI    = fmaf(cc[0], u, hI);
        hJ    = fmaf(cc[1], u, hJ);
        p2c   = fmaf(cc[2], u, p2c);
        p3c   = fmaf(cc[3], u, p3c);
        gJ    = fmaf(cc[4], u, gJ);
        ri_Au = fmaf(cc[5], au, ri_Au);
        rj_Au = fmaf(cc[6], au, rj_Au);
        rj_ca = fmaf(cc[7], u, rj_ca);
        ri_ca = fmaf(cc[8], u, ri_ca);
        t911  = fmaf(cc[9] + cc[11], u, t911);
        t1012 = fmaf(cc[10] + cc[12], u, t1012);
        t13   = fmaf(cc[13], u, t13);
        rj_ra2= fmaf(cc[14], u, rj_ra2);
        rj_n2 = fmaf(cc[17] + cc[19], u, rj_n2);
        ri_n2 = fmaf(cc[18], u, ri_n2);
    }
    float rai = g_ra[b*NN + i], cai = g_ca[b*NN + i];
    float Ri = rai*ri_ra + ri_uA + (float)NN*(ri_n + ri_n2) + ri_Au + cai*ri_ca;
    float Rj = rai*(rj_ra + rj_ra2) + rj_uA + (float)NN*(rj_n + rj_n2) + rj_Au + cai*rj_ca;

    int base = (b*ECH + e)*NN + i;
    g_P4[base] = make_float4(p01, p2c, p3c, 0.f);
    g_I4[base] = make_float4(gI, hI, mI, t14);
    g_I2[base] = make_float2(t911, Ri);
    g_J4[base] = make_float4(gJ, hJ, mJ, Rj);
    g_J2[base] = make_float2(t13, t1012);

    if (i == 0) {
        float s = 0.f;
        for (int d = 0; d < FF; d++) {
            float w = sc[d*20 + 17] + sc[d*20 + 18]
                    + sc[(d+32)*20 + 15] + sc[(d+32)*20 + 16];
            s = fmaf(w, g_su[b*FF + d], s);
        }
        g_s[b*ECH + e] = s;
    }
}

// layer-2 collapsed weights: one block per d, coalesced
__global__ void k_prepW(const float* __restrict__ c2, const float* __restrict__ b2) {
    int d = blockIdx.x, tid = threadIdx.x;
    __shared__ float sc2[ECH*20];
    __shared__ float cs[20];
    for (int idx = tid; idx < ECH*20; idx += 128)
        sc2[idx] = c2[d*(ECH*20) + idx];
    __syncthreads();
    if (tid < 20) {
        float s = 0.f;
        for (int e = 0; e < ECH; e++) s += sc2[e*20 + tid];
        cs[tid] = s;
    }
    __syncthreads();
    if (tid == 0) {
        float invn = 1.0f / (float)NN;
        g_w[0*ECH + d] = cs[15]+cs[16]+cs[17]+cs[18]+cs[19];
        g_w[1*ECH + d] = cs[5]+cs[6]+cs[7]+cs[8];
        g_w[2*ECH + d] = cs[4]*invn;
        g_w[3*ECH + d] = (cs[9]+cs[10]+cs[11]+cs[12]+cs[13])*invn;
        g_w[4*ECH + d] = cs[14]*invn;
        g_w[5*ECH + d] = (cs[0]+cs[1])*invn;
        g_w[6*ECH + d] = (cs[2]+cs[3])*invn;
    }
    if (d == 0 && tid == 32) {
        float s = 0.f;
        for (int e = 0; e < ECH; e++) s += b2[e];
        g_b2sum = s;
    }
}

// main fused kernel (f32x2 packed GEMM + epilogue)
__global__ void __launch_bounds__(256, 2) k_main(const float* __restrict__ bias1) {
    extern __shared__ float sm[];
    float*  sA  = sm;                               // 128*NP floats (66048 B)
    float2* sP1 = (float2*)(sm + NN*NP);            // 32 pairs x 64 mm
    float2* sP2 = sP1 + 32*64;
    float*  sx  = (float*)(sP2 + 32*64);
    float*  sra = sx;            // 128
    float*  sca = sx + 128;      // 128
    float*  sw  = sx + 256;      // 7*64
    float*  ssv = sx + 256 + 7*64;  // 64
    float*  sb1 = ssv + 64;         // 64

    int b = blockIdx.y, i = blockIdx.x, tid = threadIdx.x;
    int te = tid >> 5, tj = tid & 31;

    const float* Ab = g_A + b*NSQ;
    for (int idx = tid; idx < NSQ; idx += 256)
        sA[(idx >> 7)*NP + (idx & 127)] = Ab[idx];
    if (tid < 128) { sra[tid] = g_ra[b*NN + tid]; sca[tid] = g_ca[b*NN + tid]; }
    for (int idx = tid; idx < 7*ECH; idx += 256) sw[idx] = g_w[idx];
    if (tid < ECH) { ssv[tid] = g_s[b*ECH + tid]; sb1[tid] = bias1[tid]; }

    u64 acc[4][4];
    #pragma unroll
    for (int p = 0; p < 4; p++)
        #pragma unroll
        for (int q = 0; q < 4; q++) acc[p][q] = 0ULL;

    const float4* P4 = g_P4 + b*ECH*NN;

    for (int ch = 0; ch < 2; ch++) {
        int m0 = ch * 64;
        __syncthreads();
        for (int idx = tid; idx < 32*64; idx += 256) {
            int pr = idx >> 6, mm = idx & 63, m = m0 + mm;
            float ami = sA[m*NP + i];
            float aim = sA[i*NP + m];
            float4 a0 = P4[(2*pr    )*NN + m];
            float4 a1 = P4[(2*pr + 1)*NN + m];
            sP1[idx] = make_float2(fmaf(a0.x, ami, a0.y*aim),
                                   fmaf(a1.x, ami, a1.y*aim));
            sP2[idx] = make_float2(a0.z*ami, a1.z*ami);
        }
        __syncthreads();
        #pragma unroll 2
        for (int mm = 0; mm < 64; mm++) {
            int m = m0 + mm;
            u64 cvp[4], rvp[4];
            #pragma unroll
            for (int q = 0; q < 4; q++) {
                float cv = sA[m*NP + tj + 32*q];
                float rv = sA[(tj + 32*q)*NP + m];
                cvp[q] = pk2(cv, cv);
                rvp[q] = pk2(rv, rv);
            }
            #pragma unroll
            for (int pp = 0; pp < 4; pp++) {
                u64 p1 = *(const u64*)&sP1[(te*4 + pp)*64 + mm];
                u64 p2 = *(const u64*)&sP2[(te*4 + pp)*64 + mm];
                #pragma unroll
                for (int q = 0; q < 4; q++)
                    acc[pp][q] = fma2(p1, cvp[q], fma2(p2, rvp[q], acc[pp][q]));
            }
        }
    }

    // epilogue
    float rai = sra[i], cai = sca[i];
    const float4* GH = g_GH + b*NSQ + i*NN;
    float4 gh[4]; float aij[4], raj[4], caj[4];
    #pragma unroll
    for (int q = 0; q < 4; q++) {
        int j = tj + 32*q;
        gh[q]  = GH[j];
        aij[q] = sA[i*NP + j];
        raj[q] = sra[j];
        caj[q] = sca[j];
    }

    const float invn = 1.0f / (float)NN;
    float accout = 0.f;
    #pragma unroll
    for (int pp = 0; pp < 4; pp++) {
        float2 av[4];
        #pragma unroll
        for (int q = 0; q < 4; q++) av[q] = upk2(acc[pp][q]);
        #pragma unroll
        for (int half = 0; half < 2; half++) {
            int e = (te*4 + pp)*2 + half;
            int base = (b*ECH + e)*NN;
            float4 I4v = g_I4[base + i];
            float2 I2v = g_I2[base + i];
            float sv = ssv[e], b1 = sb1[e];
            float wT    = sw[0*ECH + e];
            float wTA   = sw[1*ECH + e];
            float wTG   = sw[2*ECH + e];
            float wTzRi = sw[3*ECH + e];
            float wTzRj = sw[4*ECH + e];
            float wTARi = sw[5*ECH + e];
            float wTARj = sw[6*ECH + e];
            #pragma unroll
            for (int q = 0; q < 4; q++) {
                int j = tj + 32*q;
                float4 J4v = g_J4[base + j];
                float2 J2v = g_J2[base + j];
                float accv = half ? av[q].y : av[q].x;
                float phi = accv
                    + gh[q].x * (I4v.x + J4v.x)
                    + gh[q].y * (I4v.y + J4v.y)
                    + gh[q].z * I4v.z + gh[q].w * J4v.z
                    + I2v.y + J4v.w
                    + raj[q] * I4v.w + rai * J2v.x
                    + caj[q] * I2v.x + cai * J2v.y
                    + sv;
                float pre = fmaf(phi, invn, b1);
                float z = __fdividef(1.0f, 1.0f + __expf(-pre));
                float w = wT + wTA*aij[q] + wTG*gh[q].x
                        + rai    * fmaf(wTARi, aij[q], wTzRi)
                        + raj[q] * fmaf(wTARj, aij[q], wTzRj);
                accout = fmaf(z, w, accout);
            }
        }
    }

    __shared__ float red[8];
    float v = warpSum(accout);
    if ((tid & 31) == 0) red[tid >> 5] = v;
    __syncthreads();
    if (tid == 0) {
        float s = 0.f;
        #pragma unroll
        for (int w8 = 0; w8 < 8; w8++) s += red[w8];
        g_part[b*NN + i] = s;
    }
}

__global__ void k_final(float* __restrict__ out) {
    int tid = threadIdx.x;
    __shared__ float red[4];
    for (int b = 0; b < BG; b++) {
        float v = warpSum(g_part[b*NN + tid]);
        if ((tid & 31) == 0) red[tid >> 5] = v;
        __syncthreads();
        if (tid == 0) {
            float total = red[0] + red[1] + red[2] + red[3];
            out[b] = (total + (float)NSQ * g_b2sum) * (1.0f / (float)(ECH*NSQ));
        }
        __syncthreads();
    }
}

// ---------------- launch ----------------
extern "C" void kernel_launch(void* const* d_in, const int* in_sizes, int n_in,
                              void* d_out, int out_size) {
    const float* x   = (const float*)d_in[0];
    const float* ew  = (const float*)d_in[1];
    const float* c1  = (const float*)d_in[2];
    const float* b1  = (const float*)d_in[3];
    const float* c2  = (const float*)d_in[4];
    const float* b2  = (const float*)d_in[5];
    const int*   ei  = (const int*)  d_in[6];
    const int*   bat = (const int*)  d_in[7];
    float* out = (float*)d_out;
    int ne = in_sizes[1];

    const int smemA = (NN*NP + FF*NP) * (int)sizeof(float);
    const int smemM = (NN*NP + 4*32*64 + 256 + 7*ECH + 2*ECH) * (int)sizeof(float);

    static bool attr_done = false;
    if (!attr_done) {
        cudaFuncSetAttribute(k_prepA, cudaFuncAttributeMaxDynamicSharedMemorySize, smemA);
        cudaFuncSetAttribute(k_main,  cudaFuncAttributeMaxDynamicSharedMemorySize, smemM);
        attr_done = true;
    }

    k_zeroA<<<(BG*NSQ + 255)/256, 256>>>();
    k_scatter<<<(ne + 255)/256, 256>>>(ei, ew, bat, ne);
    k_prepA<<<dim3(16, BG), 256, smemA>>>(x);
    k_prepV<<<dim3(ECH, BG), 128>>>(c1);
    k_prepW<<<ECH, 128>>>(c2, b2);
    k_main<<<dim3(NN, BG), 256, smemM>>>(b1);
    k_final<<<1, 128>>>(out);
    (void)n_in; (void)out_size;
}

// round 6
// speedup vs baseline: 1.8221x; 1.0464x over previous
#include <cuda_runtime.h>
#include <math.h>

// Shapes fixed by the problem instance:
// b=4 graphs, n=128 nodes, f=32 features, layer channels 64.
#define BG   4
#define NN   128
#define FF   32
#define ECH  64
#define NP   129
#define NSQ  (NN*NN)

typedef unsigned long long u64;

// ---------------- device scratch ----------------
__device__ float  g_A [BG*NSQ];
__device__ float4 g_GH[BG*NSQ];        // (G, H, M2, M2^T) at [b][i][j]
__device__ float  g_ra[BG*NN];
__device__ float  g_ca[BG*NN];
__device__ float  g_U [BG*FF*NN];
__device__ float  g_UA[BG*FF*NN];
__device__ float  g_Au[BG*FF*NN];
__device__ float  g_su[BG*FF];

// packed per-(b,e,pos) vectors
__device__ float4 g_P4[BG*ECH*NN];     // (p01, p2c, p3c, 0)
__device__ float4 g_I4[BG*ECH*NN];     // (gI, hI, mI, t14)
__device__ float2 g_I2[BG*ECH*NN];     // (t911, Ri)
__device__ float4 g_J4[BG*ECH*NN];     // (gJ, hJ, mJ, Rj)
__device__ float2 g_J2[BG*ECH*NN];     // (t13, t1012)
__device__ float  g_s [BG*ECH];

__device__ float g_w[7*ECH];
__device__ float g_b2sum;
__device__ float g_part[BG*NN];

__device__ __forceinline__ float warpSum(float v) {
    #pragma unroll
    for (int o = 16; o; o >>= 1) v += __shfl_down_sync(0xffffffffu, v, o);
    return v;
}
__device__ __forceinline__ u64 pk2(float lo, float hi) {
    u64 r; asm("mov.b64 %0, {%1, %2};" : "=l"(r) : "f"(lo), "f"(hi)); return r;
}
__device__ __forceinline__ float2 upk2(u64 v) {
    float2 f; asm("mov.b64 {%0, %1}, %2;" : "=f"(f.x), "=f"(f.y) : "l"(v)); return f;
}
__device__ __forceinline__ u64 fma2(u64 a, u64 b, u64 c) {
    u64 d; asm("fma.rn.f32x2 %0, %1, %2, %3;" : "=l"(d) : "l"(a), "l"(b), "l"(c)); return d;
}

// ---------------- fused init: A build (blocks 0..3) + layer-2 weights (4..67) ----
__global__ void __launch_bounds__(256) k_init(const int* __restrict__ ei,
                                              const float* __restrict__ ew,
                                              const int* __restrict__ batch,
                                              const float* __restrict__ c2,
                                              const float* __restrict__ b2,
                                              int ne) {
    extern __shared__ float sm[];
    int tid = threadIdx.x;
    if (blockIdx.x < BG) {
        int b = blockIdx.x;
        // zero smem A
        float4* s4 = (float4*)sm;
        for (int idx = tid; idx < NSQ/4; idx += 256)
            s4[idx] = make_float4(0.f, 0.f, 0.f, 0.f);
        __syncthreads();
        // scatter edges belonging to this graph
        for (int idx = tid; idx < ne; idx += 256) {
            int s = ei[idx];
            int g = batch[s];
            if (g == b) {
                int t = ei[ne + idx];
                int r = s - g*NN;
                int c = t - g*NN;
                atomicAdd(&sm[r*NN + c], ew[idx]);
            }
        }
        __syncthreads();
        // coalesced writeback
        float4* d4 = (float4*)(g_A + b*NSQ);
        for (int idx = tid; idx < NSQ/4; idx += 256)
            d4[idx] = s4[idx];
    } else {
        int d = blockIdx.x - BG;
        float* sc2 = sm;            // ECH*20
        __shared__ float cs[20];
        for (int idx = tid; idx < ECH*20; idx += 256)
            sc2[idx] = c2[d*(ECH*20) + idx];
        __syncthreads();
        if (tid < 20) {
            float s = 0.f;
            for (int e = 0; e < ECH; e++) s += sc2[e*20 + tid];
            cs[tid] = s;
        }
        __syncthreads();
        if (tid == 0) {
            float invn = 1.0f / (float)NN;
            g_w[0*ECH + d] = cs[15]+cs[16]+cs[17]+cs[18]+cs[19];
            g_w[1*ECH + d] = cs[5]+cs[6]+cs[7]+cs[8];
            g_w[2*ECH + d] = cs[4]*invn;
            g_w[3*ECH + d] = (cs[9]+cs[10]+cs[11]+cs[12]+cs[13])*invn;
            g_w[4*ECH + d] = cs[14]*invn;
            g_w[5*ECH + d] = (cs[0]+cs[1])*invn;
            g_w[6*ECH + d] = (cs[2]+cs[3])*invn;
        }
        if (d == 0 && tid == 32) {
            float s = 0.f;
            for (int e = 0; e < ECH; e++) s += b2[e];
            g_b2sum = s;
        }
    }
}

// Fused: per (b, 8-row tile): G/H/M2/M2T, UA, Au, ra, ca; tile 0: su + g_U.
__global__ void __launch_bounds__(256, 2) k_prepA(const float* __restrict__ x) {
    extern __shared__ float sm[];
    float* sA = sm;              // [128][NP]
    float* sU = sm + NN*NP;      // [32][NP]
    int b = blockIdx.y, t = blockIdx.x, tid = threadIdx.x;
    const float* Ab = g_A + b*NSQ;
    for (int idx = tid; idx < NSQ; idx += 256)
        sA[(idx >> 7)*NP + (idx & 127)] = Ab[idx];
    for (int idx = tid; idx < FF*NN; idx += 256) {
        int d = idx & 31, m = idx >> 5;
        sU[d*NP + m] = x[(b*NN + m)*FF + d];
    }
    __syncthreads();

    int r = tid >> 5, lane = tid & 31;
    int i = 8*t + r;

    float gv[4] = {0,0,0,0}, hv[4] = {0,0,0,0}, mv[4] = {0,0,0,0}, mt[4] = {0,0,0,0};
    #pragma unroll 4
    for (int k = 0; k < NN; k++) {
        float aik = sA[i*NP + k];
        float aki = sA[k*NP + i];
        #pragma unroll
        for (int q = 0; q < 4; q++) {
            int j = lane + 32*q;
            float ajk = sA[j*NP + k];
            float akj = sA[k*NP + j];
            gv[q] = fmaf(aik, ajk, gv[q]);
            hv[q] = fmaf(aki, akj, hv[q]);
            mv[q] = fmaf(aik, akj, mv[q]);
            mt[q] = fmaf(ajk, aki, mt[q]);
        }
    }
    #pragma unroll
    for (int q = 0; q < 4; q++) {
        int j = lane + 32*q;
        g_GH[b*NSQ + i*NN + j] = make_float4(gv[q], hv[q], mv[q], mt[q]);
    }

    {
        float p = 0.f;
        #pragma unroll
        for (int q = 0; q < 4; q++) p += sA[i*NP + lane + 32*q];
        p = warpSum(p);
        if (lane == 0) g_ra[b*NN + i] = p;
        int j0 = 8*t + r;
        float c = 0.f;
        #pragma unroll
        for (int q = 0; q < 4; q++) c += sA[(lane + 32*q)*NP + j0];
        c = warpSum(c);
        if (lane == 0) g_ca[b*NN + j0] = c;
    }

    {
        int d = tid >> 3, p8 = tid & 7;
        int pos = 8*t + p8;
        float ua = 0.f, au = 0.f;
        #pragma unroll 4
        for (int m = 0; m < NN; m++) {
            float um = sU[d*NP + m];
            ua = fmaf(um, sA[m*NP + pos], ua);
            au = fmaf(sA[pos*NP + m], um, au);
        }
        g_UA[(b*FF + d)*NN + pos] = ua;
        g_Au[(b*FF + d)*NN + pos] = au;
    }

    if (t == 0) {
        for (int idx = tid; idx < FF*NN; idx += 256)
            g_U[b*FF*NN + idx] = sU[(idx >> 7)*NP + (idx & 127)];
        if (tid < FF) {
            float s = 0.f;
            for (int m = 0; m < NN; m++) s += sU[tid*NP + m];
            g_su[b*FF + tid] = s;
        }
    }
}

// per (b, e-pair): smem-staged contraction of coeffs1 with U/UA/Au
__global__ void __launch_bounds__(256, 3) k_prepV(const float* __restrict__ c1) {
    extern __shared__ float sm[];
    float* sU  = sm;              // [32][128]
    float* sUA = sm + 4096;
    float* sAu = sm + 8192;
    float* sra = sm + 12288;      // 128
    float* sca = sm + 12416;      // 128
    float* sc  = sm + 12544;      // 2*64*20

    int b = blockIdx.y, eg = blockIdx.x, tid = threadIdx.x;

    {   // cooperative float4 staging: U/UA/Au = 3*1024 float4
        const float4* u4  = (const float4*)(g_U  + b*FF*NN);
        const float4* ua4 = (const float4*)(g_UA + b*FF*NN);
        const float4* au4 = (const float4*)(g_Au + b*FF*NN);
        float4* dU  = (float4*)sU;
        float4* dUA = (float4*)sUA;
        float4* dAu = (float4*)sAu;
        #pragma unroll
        for (int k = 0; k < 4; k++) {
            int idx = tid + 256*k;
            dU [idx] = u4 [idx];
            dUA[idx] = ua4[idx];
            dAu[idx] = au4[idx];
        }
        if (tid < 128) { sra[tid] = g_ra[b*NN + tid]; sca[tid] = g_ca[b*NN + tid]; }
        for (int idx = tid; idx < 2*64*20; idx += 256) {
            int s = idx / 1280, rem = idx - s*1280;
            int d = rem / 20, r = rem - d*20;
            sc[idx] = c1[d*(ECH*20) + (2*eg + s)*20 + r];
        }
    }
    __syncthreads();

    int sub = tid >> 7, i = tid & 127;
    int e = 2*eg + sub;
    const float* scb = sc + sub*1280;

    float p01=0, p2c=0, p3c=0, gI=0, gJ=0, hI=0, hJ=0, mI=0, mJ=0;
    float t14=0, t13=0, t911=0, t1012=0;
    float ri_ra=0, ri_uA=0, ri_n=0, ri_Au=0, ri_ca=0, ri_n2=0;
    float rj_ra=0, rj_uA=0, rj_n=0, rj_Au=0, rj_ca=0, rj_ra2=0, rj_n2=0;

    #pragma unroll 8
    for (int d = 0; d < FF; d++) {
        float u  = sU [d*NN + i];
        float ua = sUA[d*NN + i];
        float au = sAu[d*NN + i];
        const float* cr = scb + d*20;
        const float* cc = scb + (d + 32)*20;
        p01   = fmaf(cr[0] + cr[1], u, p01);
        mI    = fmaf(cr[2], u, mI);
        mJ    = fmaf(cr[3], u, mJ);
        gI    = fmaf(cr[4], u, gI);
        ri_ra = fmaf(cr[5] + cr[13], u, ri_ra);
        rj_ra = fmaf(cr[6], u, rj_ra);
        rj_uA = fmaf(cr[7] + cr[9] + cr[11], ua, rj_uA);
        ri_uA = fmaf(cr[8] + cr[10] + cr[12], ua, ri_uA);
        t14   = fmaf(cr[14], u, t14);
        ri_n  = fmaf(cr[15] + cr[19], u, ri_n);
        rj_n  = fmaf(cr[16], u, rj_n);
        hI    = fmaf(cc[0], u, hI);
        hJ    = fmaf(cc[1], u, hJ);
        p2c   = fmaf(cc[2], u, p2c);
        p3c   = fmaf(cc[3], u, p3c);
        gJ    = fmaf(cc[4], u, gJ);
        ri_Au = fmaf(cc[5], au, ri_Au);
        rj_Au = fmaf(cc[6], au, rj_Au);
        rj_ca = fmaf(cc[7], u, rj_ca);
        ri_ca = fmaf(cc[8], u, ri_ca);
        t911  = fmaf(cc[9] + cc[11], u, t911);
        t1012 = fmaf(cc[10] + cc[12], u, t1012);
        t13   = fmaf(cc[13], u, t13);
        rj_ra2= fmaf(cc[14], u, rj_ra2);
        rj_n2 = fmaf(cc[17] + cc[19], u, rj_n2);
        ri_n2 = fmaf(cc[18], u, ri_n2);
    }
    float rai = sra[i], cai = sca[i];
    float Ri = rai*ri_ra + ri_uA + (float)NN*(ri_n + ri_n2) + ri_Au + cai*ri_ca;
    float Rj = rai*(rj_ra + rj_ra2) + rj_uA + (float)NN*(rj_n + rj_n2) + rj_Au + cai*rj_ca;

    int base = (b*ECH + e)*NN + i;
    g_P4[base] = make_float4(p01, p2c, p3c, 0.f);
    g_I4[base] = make_float4(gI, hI, mI, t14);
    g_I2[base] = make_float2(t911, Ri);
    g_J4[base] = make_float4(gJ, hJ, mJ, Rj);
    g_J2[base] = make_float2(t13, t1012);

    if (i == 0) {
        float s = 0.f;
        for (int d = 0; d < FF; d++) {
            float w = scb[d*20 + 17] + scb[d*20 + 18]
                    + scb[(d+32)*20 + 15] + scb[(d+32)*20 + 16];
            s = fmaf(w, g_su[b*FF + d], s);
        }
        g_s[b*ECH + e] = s;
    }
}

// main fused kernel (f32x2 packed GEMM + epilogue)
__global__ void __launch_bounds__(256, 2) k_main(const float* __restrict__ bias1) {
    extern __shared__ float sm[];
    float*  sA  = sm;                               // 128*NP floats
    float2* sP1 = (float2*)(sm + NN*NP);            // 32 pairs x 64 mm
    float2* sP2 = sP1 + 32*64;
    float*  sx  = (float*)(sP2 + 32*64);
    float*  sra = sx;            // 128
    float*  sca = sx + 128;      // 128
    float*  sw  = sx + 256;      // 7*64
    float*  ssv = sx + 256 + 7*64;  // 64
    float*  sb1 = ssv + 64;         // 64

    int b = blockIdx.y, i = blockIdx.x, tid = threadIdx.x;
    int te = tid >> 5, tj = tid & 31;

    const float* Ab = g_A + b*NSQ;
    for (int idx = tid; idx < NSQ; idx += 256)
        sA[(idx >> 7)*NP + (idx & 127)] = Ab[idx];
    if (tid < 128) { sra[tid] = g_ra[b*NN + tid]; sca[tid] = g_ca[b*NN + tid]; }
    for (int idx = tid; idx < 7*ECH; idx += 256) sw[idx] = g_w[idx];
    if (tid < ECH) { ssv[tid] = g_s[b*ECH + tid]; sb1[tid] = bias1[tid]; }

    u64 acc[4][4];
    #pragma unroll
    for (int p = 0; p < 4; p++)
        #pragma unroll
        for (int q = 0; q < 4; q++) acc[p][q] = 0ULL;

    const float4* P4 = g_P4 + b*ECH*NN;

    for (int ch = 0; ch < 2; ch++) {
        int m0 = ch * 64;
        __syncthreads();
        for (int idx = tid; idx < 32*64; idx += 256) {
            int pr = idx >> 6, mm = idx & 63, m = m0 + mm;
            float ami = sA[m*NP + i];
            float aim = sA[i*NP + m];
            float4 a0 = P4[(2*pr    )*NN + m];
            float4 a1 = P4[(2*pr + 1)*NN + m];
            sP1[idx] = make_float2(fmaf(a0.x, ami, a0.y*aim),
                                   fmaf(a1.x, ami, a1.y*aim));
            sP2[idx] = make_float2(a0.z*ami, a1.z*ami);
        }
        __syncthreads();
        #pragma unroll 2
        for (int mm = 0; mm < 64; mm++) {
            int m = m0 + mm;
            u64 cvp[4], rvp[4];
            #pragma unroll
            for (int q = 0; q < 4; q++) {
                float cv = sA[m*NP + tj + 32*q];
                float rv = sA[(tj + 32*q)*NP + m];
                cvp[q] = pk2(cv, cv);
                rvp[q] = pk2(rv, rv);
            }
            #pragma unroll
            for (int pp = 0; pp < 4; pp++) {
                u64 p1 = *(const u64*)&sP1[(te*4 + pp)*64 + mm];
                u64 p2 = *(const u64*)&sP2[(te*4 + pp)*64 + mm];
                #pragma unroll
                for (int q = 0; q < 4; q++)
                    acc[pp][q] = fma2(p1, cvp[q], fma2(p2, rvp[q], acc[pp][q]));
            }
        }
    }

    // epilogue
    float rai = sra[i], cai = sca[i];
    const float4* GH = g_GH + b*NSQ + i*NN;
    float4 gh[4]; float aij[4], raj[4], caj[4];
    #pragma unroll
    for (int q = 0; q < 4; q++) {
        int j = tj + 32*q;
        gh[q]  = GH[j];
        aij[q] = sA[i*NP + j];
        raj[q] = sra[j];
        caj[q] = sca[j];
    }

    const float invn = 1.0f / (float)NN;
    float accout = 0.f;
    #pragma unroll
    for (int pp = 0; pp < 4; pp++) {
        float2 av[4];
        #pragma unroll
        for (int q = 0; q < 4; q++) av[q] = upk2(acc[pp][q]);
        #pragma unroll
        for (int half = 0; half < 2; half++) {
            int e = (te*4 + pp)*2 + half;
            int base = (b*ECH + e)*NN;
            float4 I4v = g_I4[base + i];
            float2 I2v = g_I2[base + i];
            float sv = ssv[e], b1 = sb1[e];
            float wT    = sw[0*ECH + e];
            float wTA   = sw[1*ECH + e];
            float wTG   = sw[2*ECH + e];
            float wTzRi = sw[3*ECH + e];
            float wTzRj = sw[4*ECH + e];
            float wTARi = sw[5*ECH + e];
            float wTARj = sw[6*ECH + e];
            #pragma unroll
            for (int q = 0; q < 4; q++) {
                int j = tj + 32*q;
                float4 J4v = g_J4[base + j];
                float2 J2v = g_J2[base + j];
                float accv = half ? av[q].y : av[q].x;
                float phi = accv
                    + gh[q].x * (I4v.x + J4v.x)
                    + gh[q].y * (I4v.y + J4v.y)
                    + gh[q].z * I4v.z + gh[q].w * J4v.z
                    + I2v.y + J4v.w
                    + raj[q] * I4v.w + rai * J2v.x
                    + caj[q] * I2v.x + cai * J2v.y
                    + sv;
                float pre = fmaf(phi, invn, b1);
                float z = __fdividef(1.0f, 1.0f + __expf(-pre));
                float w = wT + wTA*aij[q] + wTG*gh[q].x
                        + rai    * fmaf(wTARi, aij[q], wTzRi)
                        + raj[q] * fmaf(wTARj, aij[q], wTzRj);
                accout = fmaf(z, w, accout);
            }
        }
    }

    __shared__ float red[8];
    float v = warpSum(accout);
    if ((tid & 31) == 0) red[tid >> 5] = v;
    __syncthreads();
    if (tid == 0) {
        float s = 0.f;
        #pragma unroll
        for (int w8 = 0; w8 < 8; w8++) s += red[w8];
        g_part[b*NN + i] = s;
    }
}

__global__ void k_final(float* __restrict__ out) {
    int tid = threadIdx.x;
    __shared__ float red[4];
    for (int b = 0; b < BG; b++) {
        float v = warpSum(g_part[b*NN + tid]);
        if ((tid & 31) == 0) red[tid >> 5] = v;
        __syncthreads();
        if (tid == 0) {
            float total = red[0] + red[1] + red[2] + red[3];
            out[b] = (total + (float)NSQ * g_b2sum) * (1.0f / (float)(ECH*NSQ));
        }
        __syncthreads();
    }
}

// ---------------- launch ----------------
extern "C" void kernel_launch(void* const* d_in, const int* in_sizes, int n_in,
                              void* d_out, int out_size) {
    const float* x   = (const float*)d_in[0];
    const float* ew  = (const float*)d_in[1];
    const float* c1  = (const float*)d_in[2];
    const float* b1  = (const float*)d_in[3];
    const float* c2  = (const float*)d_in[4];
    const float* b2  = (const float*)d_in[5];
    const int*   ei  = (const int*)  d_in[6];
    const int*   bat = (const int*)  d_in[7];
    float* out = (float*)d_out;
    int ne = in_sizes[1];

    const int smemI = NSQ * (int)sizeof(float);                              // 64 KB
    const int smemA = (NN*NP + FF*NP) * (int)sizeof(float);
    const int smemV = (3*FF*NN + 256 + 2*ECH*20) * (int)sizeof(float);
    const int smemM = (NN*NP + 4*32*64 + 256 + 7*ECH + 2*ECH) * (int)sizeof(float);

    static bool attr_done = false;
    if (!attr_done) {
        cudaFuncSetAttribute(k_init,  cudaFuncAttributeMaxDynamicSharedMemorySize, smemI);
        cudaFuncSetAttribute(k_prepA, cudaFuncAttributeMaxDynamicSharedMemorySize, smemA);
        cudaFuncSetAttribute(k_prepV, cudaFuncAttributeMaxDynamicSharedMemorySize, smemV);
        cudaFuncSetAttribute(k_main,  cudaFuncAttributeMaxDynamicSharedMemorySize, smemM);
        attr_done = true;
    }

    k_init <<<BG + ECH, 256, smemI>>>(ei, ew, bat, c2, b2, ne);
    k_prepA<<<dim3(16, BG), 256, smemA>>>(x);
    k_prepV<<<dim3(ECH/2, BG), 256, smemV>>>(c1);
    k_main <<<dim3(NN, BG), 256, smemM>>>(b1);
    k_final<<<1, 128>>>(out);
    (void)n_in; (void)out_size;
}

// round 8
// speedup vs baseline: 1.8798x; 1.0317x over previous
#include <cuda_runtime.h>
#include <math.h>

// Shapes fixed by the problem instance:
// b=4 graphs, n=128 nodes, f=32 features, layer channels 64.
#define BG   4
#define NN   128
#define FF   32
#define ECH  64
#define NP   129     // padding for prepA smem
#define NPM  130     // padding for k_main smem (even -> 8B-aligned float2 rows)
#define NSQ  (NN*NN)

typedef unsigned long long u64;

// ---------------- device scratch ----------------
__device__ float  g_A [BG*NSQ];
__device__ float4 g_GH[BG*NSQ];        // (G, H, M2, M2^T) at [b][i][j]
__device__ float  g_ra[BG*NN];
__device__ float  g_ca[BG*NN];
__device__ float  g_U [BG*FF*NN];
__device__ float  g_UA[BG*FF*NN];
__device__ float  g_Au[BG*FF*NN];
__device__ float  g_su[BG*FF];

// packed per-(b,e,pos) vectors
__device__ float4 g_P4[BG*ECH*NN];     // (p01, p2c, p3c, 0)
__device__ float4 g_I4[BG*ECH*NN];     // (gI, hI, mI, t14)
__device__ float2 g_I2[BG*ECH*NN];     // (t911, Ri)
__device__ float4 g_J4[BG*ECH*NN];     // (gJ, hJ, mJ, Rj)
__device__ float2 g_J2[BG*ECH*NN];     // (t13, t1012)
__device__ float  g_s [BG*ECH];

__device__ float g_w[7*ECH];
__device__ float g_b2sum;

__device__ __forceinline__ float warpSum(float v) {
    #pragma unroll
    for (int o = 16; o; o >>= 1) v += __shfl_down_sync(0xffffffffu, v, o);
    return v;
}
__device__ __forceinline__ u64 pk2(float lo, float hi) {
    u64 r; asm("mov.b64 %0, {%1, %2};" : "=l"(r) : "f"(lo), "f"(hi)); return r;
}
__device__ __forceinline__ float2 upk2(u64 v) {
    float2 f; asm("mov.b64 {%0, %1}, %2;" : "=f"(f.x), "=f"(f.y) : "l"(v)); return f;
}
__device__ __forceinline__ u64 fma2(u64 a, u64 b, u64 c) {
    u64 d; asm("fma.rn.f32x2 %0, %1, %2, %3;" : "=l"(d) : "l"(a), "l"(b), "l"(c)); return d;
}

// ---------------- fused init: A build (blocks 0..3) + layer-2 weights (4..67) ----
__global__ void __launch_bounds__(256) k_init(const int* __restrict__ ei,
                                              const float* __restrict__ ew,
                                              const int* __restrict__ batch,
                                              const float* __restrict__ c2,
                                              const float* __restrict__ b2,
                                              float* __restrict__ out,
                                              int ne) {
    extern __shared__ float sm[];
    int tid = threadIdx.x;
    if (blockIdx.x < BG) {
        int b = blockIdx.x;
        if (tid == 0) out[b] = 0.0f;     // k_main accumulates atomically
        float4* s4 = (float4*)sm;
        for (int idx = tid; idx < NSQ/4; idx += 256)
            s4[idx] = make_float4(0.f, 0.f, 0.f, 0.f);
        __syncthreads();
        for (int idx = tid; idx < ne; idx += 256) {
            int s = ei[idx];
            int g = batch[s];
            if (g == b) {
                int t = ei[ne + idx];
                int r = s - g*NN;
                int c = t - g*NN;
                atomicAdd(&sm[r*NN + c], ew[idx]);
            }
        }
        __syncthreads();
        float4* d4 = (float4*)(g_A + b*NSQ);
        for (int idx = tid; idx < NSQ/4; idx += 256)
            d4[idx] = s4[idx];
    } else {
        int d = blockIdx.x - BG;
        float* sc2 = sm;            // ECH*20
        __shared__ float cs[20];
        for (int idx = tid; idx < ECH*20; idx += 256)
            sc2[idx] = c2[d*(ECH*20) + idx];
        __syncthreads();
        if (tid < 20) {
            float s = 0.f;
            for (int e = 0; e < ECH; e++) s += sc2[e*20 + tid];
            cs[tid] = s;
        }
        __syncthreads();
        if (tid == 0) {
            float invn = 1.0f / (float)NN;
            g_w[0*ECH + d] = cs[15]+cs[16]+cs[17]+cs[18]+cs[19];
            g_w[1*ECH + d] = cs[5]+cs[6]+cs[7]+cs[8];
            g_w[2*ECH + d] = cs[4]*invn;
            g_w[3*ECH + d] = (cs[9]+cs[10]+cs[11]+cs[12]+cs[13])*invn;
            g_w[4*ECH + d] = cs[14]*invn;
            g_w[5*ECH + d] = (cs[0]+cs[1])*invn;
            g_w[6*ECH + d] = (cs[2]+cs[3])*invn;
        }
        if (d == 0 && tid == 32) {
            float s = 0.f;
            for (int e = 0; e < ECH; e++) s += b2[e];
            g_b2sum = s;
        }
    }
}

// Fused: per (b, 8-row tile): G/H/M2/M2T, UA, Au, ra, ca; tile 0: su + g_U.
__global__ void __launch_bounds__(256, 2) k_prepA(const float* __restrict__ x) {
    extern __shared__ float sm[];
    float* sA = sm;              // [128][NP]
    float* sU = sm + NN*NP;      // [32][NP]
    int b = blockIdx.y, t = blockIdx.x, tid = threadIdx.x;
    const float* Ab = g_A + b*NSQ;
    for (int idx = tid; idx < NSQ; idx += 256)
        sA[(idx >> 7)*NP + (idx & 127)] = Ab[idx];
    for (int idx = tid; idx < FF*NN; idx += 256) {
        int d = idx & 31, m = idx >> 5;
        sU[d*NP + m] = x[(b*NN + m)*FF + d];
    }
    __syncthreads();

    int r = tid >> 5, lane = tid & 31;
    int i = 8*t + r;

    float gv[4] = {0,0,0,0}, hv[4] = {0,0,0,0}, mv[4] = {0,0,0,0}, mt[4] = {0,0,0,0};
    #pragma unroll 4
    for (int k = 0; k < NN; k++) {
        float aik = sA[i*NP + k];
        float aki = sA[k*NP + i];
        #pragma unroll
        for (int q = 0; q < 4; q++) {
            int j = lane + 32*q;
            float ajk = sA[j*NP + k];
            float akj = sA[k*NP + j];
            gv[q] = fmaf(aik, ajk, gv[q]);
            hv[q] = fmaf(aki, akj, hv[q]);
            mv[q] = fmaf(aik, akj, mv[q]);
            mt[q] = fmaf(ajk, aki, mt[q]);
        }
    }
    #pragma unroll
    for (int q = 0; q < 4; q++) {
        int j = lane + 32*q;
        g_GH[b*NSQ + i*NN + j] = make_float4(gv[q], hv[q], mv[q], mt[q]);
    }

    {
        float p = 0.f;
        #pragma unroll
        for (int q = 0; q < 4; q++) p += sA[i*NP + lane + 32*q];
        p = warpSum(p);
        if (lane == 0) g_ra[b*NN + i] = p;
        int j0 = 8*t + r;
        float c = 0.f;
        #pragma unroll
        for (int q = 0; q < 4; q++) c += sA[(lane + 32*q)*NP + j0];
        c = warpSum(c);
        if (lane == 0) g_ca[b*NN + j0] = c;
    }

    {
        int d = tid >> 3, p8 = tid & 7;
        int pos = 8*t + p8;
        float ua = 0.f, au = 0.f;
        #pragma unroll 4
        for (int m = 0; m < NN; m++) {
            float um = sU[d*NP + m];
            ua = fmaf(um, sA[m*NP + pos], ua);
            au = fmaf(sA[pos*NP + m], um, au);
        }
        g_UA[(b*FF + d)*NN + pos] = ua;
        g_Au[(b*FF + d)*NN + pos] = au;
    }

    if (t == 0) {
        for (int idx = tid; idx < FF*NN; idx += 256)
            g_U[b*FF*NN + idx] = sU[(idx >> 7)*NP + (idx & 127)];
        if (tid < FF) {
            float s = 0.f;
            for (int m = 0; m < NN; m++) s += sU[tid*NP + m];
            g_su[b*FF + tid] = s;
        }
    }
}

// per (b, e-pair): smem-staged contraction of coeffs1 with U/UA/Au
__global__ void __launch_bounds__(256, 3) k_prepV(const float* __restrict__ c1) {
    extern __shared__ float sm[];
    float* sU  = sm;              // [32][128]
    float* sUA = sm + 4096;
    float* sAu = sm + 8192;
    float* sra = sm + 12288;      // 128
    float* sca = sm + 12416;      // 128
    float* sc  = sm + 12544;      // 2*64*20

    int b = blockIdx.y, eg = blockIdx.x, tid = threadIdx.x;

    {
        const float4* u4  = (const float4*)(g_U  + b*FF*NN);
        const float4* ua4 = (const float4*)(g_UA + b*FF*NN);
        const float4* au4 = (const float4*)(g_Au + b*FF*NN);
        float4* dU  = (float4*)sU;
        float4* dUA = (float4*)sUA;
        float4* dAu = (float4*)sAu;
        #pragma unroll
        for (int k = 0; k < 4; k++) {
            int idx = tid + 256*k;
            dU [idx] = u4 [idx];
            dUA[idx] = ua4[idx];
            dAu[idx] = au4[idx];
        }
        if (tid < 128) { sra[tid] = g_ra[b*NN + tid]; sca[tid] = g_ca[b*NN + tid]; }
        for (int idx = tid; idx < 2*64*20; idx += 256) {
            int s = idx / 1280, rem = idx - s*1280;
            int d = rem / 20, r = rem - d*20;
            sc[idx] = c1[d*(ECH*20) + (2*eg + s)*20 + r];
        }
    }
    __syncthreads();

    int sub = tid >> 7, i = tid & 127;
    int e = 2*eg + sub;
    const float* scb = sc + sub*1280;

    float p01=0, p2c=0, p3c=0, gI=0, gJ=0, hI=0, hJ=0, mI=0, mJ=0;
    float t14=0, t13=0, t911=0, t1012=0;
    float ri_ra=0, ri_uA=0, ri_n=0, ri_Au=0, ri_ca=0, ri_n2=0;
    float rj_ra=0, rj_uA=0, rj_n=0, rj_Au=0, rj_ca=0, rj_ra2=0, rj_n2=0;

    #pragma unroll 8
    for (int d = 0; d < FF; d++) {
        float u  = sU [d*NN + i];
        float ua = sUA[d*NN + i];
        float au = sAu[d*NN + i];
        const float* cr = scb + d*20;
        const float* cc = scb + (d + 32)*20;
        p01   = fmaf(cr[0] + cr[1], u, p01);
        mI    = fmaf(cr[2], u, mI);
        mJ    = fmaf(cr[3], u, mJ);
        gI    = fmaf(cr[4], u, gI);
        ri_ra = fmaf(cr[5] + cr[13], u, ri_ra);
        rj_ra = fmaf(cr[6], u, rj_ra);
        rj_uA = fmaf(cr[7] + cr[9] + cr[11], ua, rj_uA);
        ri_uA = fmaf(cr[8] + cr[10] + cr[12], ua, ri_uA);
        t14   = fmaf(cr[14], u, t14);
        ri_n  = fmaf(cr[15] + cr[19], u, ri_n);
        rj_n  = fmaf(cr[16], u, rj_n);
        hI    = fmaf(cc[0], u, hI);
        hJ    = fmaf(cc[1], u, hJ);
        p2c   = fmaf(cc[2], u, p2c);
        p3c   = fmaf(cc[3], u, p3c);
        gJ    = fmaf(cc[4], u, gJ);
        ri_Au = fmaf(cc[5], au, ri_Au);
        rj_Au = fmaf(cc[6], au, rj_Au);
        rj_ca = fmaf(cc[7], u, rj_ca);
        ri_ca = fmaf(cc[8], u, ri_ca);
        t911  = fmaf(cc[9] + cc[11], u, t911);
        t1012 = fmaf(cc[10] + cc[12], u, t1012);
        t13   = fmaf(cc[13], u, t13);
        rj_ra2= fmaf(cc[14], u, rj_ra2);
        rj_n2 = fmaf(cc[17] + cc[19], u, rj_n2);
        ri_n2 = fmaf(cc[18], u, ri_n2);
    }
    float rai = sra[i], cai = sca[i];
    float Ri = rai*ri_ra + ri_uA + (float)NN*(ri_n + ri_n2) + ri_Au + cai*ri_ca;
    float Rj = rai*(rj_ra + rj_ra2) + rj_uA + (float)NN*(rj_n + rj_n2) + rj_Au + cai*rj_ca;

    int base = (b*ECH + e)*NN + i;
    g_P4[base] = make_float4(p01, p2c, p3c, 0.f);
    g_I4[base] = make_float4(gI, hI, mI, t14);
    g_I2[base] = make_float2(t911, Ri);
    g_J4[base] = make_float4(gJ, hJ, mJ, Rj);
    g_J2[base] = make_float2(t13, t1012);

    if (i == 0) {
        float s = 0.f;
        for (int d = 0; d < FF; d++) {
            float w = scb[d*20 + 17] + scb[d*20 + 18]
                    + scb[(d+32)*20 + 15] + scb[(d+32)*20 + 16];
            s = fmaf(w, g_su[b*FF + d], s);
        }
        g_s[b*ECH + e] = s;
    }
}

// main fused kernel: 2 i per block (single balanced wave), f32x2 packed GEMM,
// mm-pair inner loop with vector sP loads, fused final reduction via atomics.
__global__ void __launch_bounds__(256, 2) k_main(const float* __restrict__ bias1,
                                                 float* __restrict__ out) {
    extern __shared__ float sm[];
    float*  sA  = sm;                               // 128*NPM floats
    float2* sP1 = (float2*)(sm + NN*NPM);           // [32 e-pairs][64 mm]
    float2* sP2 = sP1 + 32*64;
    float*  sx  = (float*)(sP2 + 32*64);
    float*  sra = sx;               // 128
    float*  sca = sx + 128;         // 128
    float*  sw  = sx + 256;         // 7*64
    float*  ssv = sx + 256 + 7*64;  // 64
    float*  sb1 = ssv + 64;         // 64

    int b = blockIdx.y, bx = blockIdx.x, tid = threadIdx.x;
    int te = tid >> 5, tj = tid & 31;

    const float* Ab = g_A + b*NSQ;
    for (int idx = tid; idx < NSQ; idx += 256)
        sA[(idx >> 7)*NPM + (idx & 127)] = Ab[idx];
    if (tid < 128) { sra[tid] = g_ra[b*NN + tid]; sca[tid] = g_ca[b*NN + tid]; }
    for (int idx = tid; idx < 7*ECH; idx += 256) sw[idx] = g_w[idx];
    if (tid < ECH) { ssv[tid] = g_s[b*ECH + tid]; sb1[tid] = bias1[tid]; }

    const float4* P4 = g_P4 + b*ECH*NN;
    const float invn = 1.0f / (float)NN;
    const float scale = 1.0f / (float)(ECH*NSQ);
    __shared__ float red[8];

    for (int ii = 0; ii < 2; ii++) {
        int i = 2*bx + ii;

        u64 acc[4][4];
        #pragma unroll
        for (int p = 0; p < 4; p++)
            #pragma unroll
            for (int q = 0; q < 4; q++) acc[p][q] = 0ULL;

        for (int ch = 0; ch < 2; ch++) {
            int m0 = ch * 64;
            __syncthreads();
            for (int idx = tid; idx < 32*64; idx += 256) {
                int pr = idx >> 6, mm = idx & 63, m = m0 + mm;
                float ami = sA[m*NPM + i];
                float aim = sA[i*NPM + m];
                float4 a0 = P4[(2*pr    )*NN + m];
                float4 a1 = P4[(2*pr + 1)*NN + m];
                sP1[idx] = make_float2(fmaf(a0.x, ami, a0.y*aim),
                                       fmaf(a1.x, ami, a1.y*aim));
                sP2[idx] = make_float2(a0.z*ami, a1.z*ami);
            }
            __syncthreads();
            for (int mm = 0; mm < 64; mm += 2) {
                int m = m0 + mm;
                u64 cv0[4], cv1[4], rv0[4], rv1[4];
                #pragma unroll
                for (int q = 0; q < 4; q++) {
                    int j = tj + 32*q;
                    float c0 = sA[m*NPM + j];
                    float c1v = sA[(m+1)*NPM + j];
                    float2 rr = *(const float2*)&sA[j*NPM + m];
                    cv0[q] = pk2(c0, c0);
                    cv1[q] = pk2(c1v, c1v);
                    rv0[q] = pk2(rr.x, rr.x);
                    rv1[q] = pk2(rr.y, rr.y);
                }
                #pragma unroll
                for (int pp = 0; pp < 4; pp++) {
                    ulonglong2 p1v = *(const ulonglong2*)&sP1[(te*4 + pp)*64 + mm];
                    ulonglong2 p2v = *(const ulonglong2*)&sP2[(te*4 + pp)*64 + mm];
                    #pragma unroll
                    for (int q = 0; q < 4; q++) {
                        acc[pp][q] = fma2(p1v.x, cv0[q], fma2(p2v.x, rv0[q], acc[pp][q]));
                        acc[pp][q] = fma2(p1v.y, cv1[q], fma2(p2v.y, rv1[q], acc[pp][q]));
                    }
                }
            }
        }

        // epilogue
        float rai = sra[i], cai = sca[i];
        const float4* GH = g_GH + b*NSQ + i*NN;
        float4 gh[4]; float aij[4], raj[4], caj[4];
        #pragma unroll
        for (int q = 0; q < 4; q++) {
            int j = tj + 32*q;
            gh[q]  = GH[j];
            aij[q] = sA[i*NPM + j];
            raj[q] = sra[j];
            caj[q] = sca[j];
        }

        float accout = 0.f;
        #pragma unroll
        for (int pp = 0; pp < 4; pp++) {
            float2 av[4];
            #pragma unroll
            for (int q = 0; q < 4; q++) av[q] = upk2(acc[pp][q]);
            #pragma unroll
            for (int half = 0; half < 2; half++) {
                int e = (te*4 + pp)*2 + half;
                int base = (b*ECH + e)*NN;
                float4 I4v = g_I4[base + i];
                float2 I2v = g_I2[base + i];
                float sv = ssv[e], b1 = sb1[e];
                float wT    = sw[0*ECH + e];
                float wTA   = sw[1*ECH + e];
                float wTG   = sw[2*ECH + e];
                float wTzRi = sw[3*ECH + e];
                float wTzRj = sw[4*ECH + e];
                float wTARi = sw[5*ECH + e];
                float wTARj = sw[6*ECH + e];
                #pragma unroll
                for (int q = 0; q < 4; q++) {
                    int j = tj + 32*q;
                    float4 J4v = g_J4[base + j];
                    float2 J2v = g_J2[base + j];
                    float accv = half ? av[q].y : av[q].x;
                    float phi = accv
                        + gh[q].x * (I4v.x + J4v.x)
                        + gh[q].y * (I4v.y + J4v.y)
                        + gh[q].z * I4v.z + gh[q].w * J4v.z
                        + I2v.y + J4v.w
                        + raj[q] * I4v.w + rai * J2v.x
                        + caj[q] * I2v.x + cai * J2v.y
                        + sv;
                    float pre = fmaf(phi, invn, b1);
                    float z = __fdividef(1.0f, 1.0f + __expf(-pre));
                    float w = wT + wTA*aij[q] + wTG*gh[q].x
                            + rai    * fmaf(wTARi, aij[q], wTzRi)
                            + raj[q] * fmaf(wTARj, aij[q], wTzRj);
                    accout = fmaf(z, w, accout);
                }
            }
        }

        float v = warpSum(accout);
        if ((tid & 31) == 0) red[tid >> 5] = v;
        __syncthreads();
        if (tid == 0) {
            float s = 0.f;
            #pragma unroll
            for (int w8 = 0; w8 < 8; w8++) s += red[w8];
            if (bx == 0 && ii == 0) s += (float)NSQ * g_b2sum;
            atomicAdd(&out[b], s * scale);
        }
        __syncthreads();
    }
}

// ---------------- launch ----------------
extern "C" void kernel_launch(void* const* d_in, const int* in_sizes, int n_in,
                              void* d_out, int out_size) {
    const float* x   = (const float*)d_in[0];
    const float* ew  = (const float*)d_in[1];
    const float* c1  = (const float*)d_in[2];
    const float* b1  = (const float*)d_in[3];
    const float* c2  = (const float*)d_in[4];
    const float* b2  = (const float*)d_in[5];
    const int*   ei  = (const int*)  d_in[6];
    const int*   bat = (const int*)  d_in[7];
    float* out = (float*)d_out;
    int ne = in_sizes[1];

    const int smemI = NSQ * (int)sizeof(float);                               // 64 KB
    const int smemA = (NN*NP + FF*NP) * (int)sizeof(float);
    const int smemV = (3*FF*NN + 256 + 2*ECH*20) * (int)sizeof(float);
    const int smemM = (NN*NPM + 4*32*64 + 256 + 7*ECH + 2*ECH) * (int)sizeof(float);

    static bool attr_done = false;
    if (!attr_done) {
        cudaFuncSetAttribute(k_init,  cudaFuncAttributeMaxDynamicSharedMemorySize, smemI);
        cudaFuncSetAttribute(k_prepA, cudaFuncAttributeMaxDynamicSharedMemorySize, smemA);
        cudaFuncSetAttribute(k_prepV, cudaFuncAttributeMaxDynamicSharedMemorySize, smemV);
        cudaFuncSetAttribute(k_main,  cudaFuncAttributeMaxDynamicSharedMemorySize, smemM);
        attr_done = true;
    }

    k_init <<<BG + ECH, 256, smemI>>>(ei, ew, bat, c2, b2, out, ne);
    k_prepA<<<dim3(16, BG), 256, smemA>>>(x);
    k_prepV<<<dim3(ECH/2, BG), 256, smemV>>>(c1);
    k_main <<<dim3(NN/2, BG), 256, smemM>>>(b1, out);
    (void)n_in; (void)out_size;
}